// round 4
// baseline (speedup 1.0000x reference)
#include <cuda_runtime.h>
#include <cuda_fp16.h>
#include <stdint.h>

#define M_DIM 2048
#define N_DIM 11008
#define K_DIM 4096

#define BM 128
#define BN 256
#define BK 64
#define KT (K_DIM / BK)      // 64
#define STAGES 3

#define LDA_B 144            // A row stride bytes (128 + 16 pad)
#define LDB_B 528            // B row stride bytes (512 + 16 pad)
#define A_SZ (BM * LDA_B)    // 18432
#define B_SZ (BK * LDB_B)    // 33792
#define STAGE_SZ (A_SZ + B_SZ)           // 52224
#define SMEM_TOTAL (STAGES * STAGE_SZ)   // 156672

__device__ __half g_xh[(size_t)M_DIM * K_DIM];   // x in fp16
__device__ __half g_wt[(size_t)K_DIM * N_DIM];   // dequantized W, [K][N]

// ---------------------------------------------------------------------------
__global__ void convert_x_kernel(const float* __restrict__ x) {
    size_t i = ((size_t)blockIdx.x * blockDim.x + threadIdx.x) * 8;
    float4 f0 = *(const float4*)(x + i);
    float4 f1 = *(const float4*)(x + i + 4);
    __half2 h01 = __floats2half2_rn(f0.x, f0.y);
    __half2 h23 = __floats2half2_rn(f0.z, f0.w);
    __half2 h45 = __floats2half2_rn(f1.x, f1.y);
    __half2 h67 = __floats2half2_rn(f1.z, f1.w);
    uint4 v;
    v.x = *(uint32_t*)&h01; v.y = *(uint32_t*)&h23;
    v.z = *(uint32_t*)&h45; v.w = *(uint32_t*)&h67;
    *(uint4*)(g_xh + i) = v;
}

// ---------------------------------------------------------------------------
// Dequant: word (k4, n) -> wt[4*k4+j][n] = half((byte j) - zero[n])  (exact)
// Thread handles 2 adjacent n (one uint2), writes 4 half2 rows.
// ---------------------------------------------------------------------------
__global__ void dequant_kernel(const uint32_t* __restrict__ qw,
                               const int* __restrict__ zeros) {
    size_t idx = (size_t)blockIdx.x * blockDim.x + threadIdx.x;  // word pair
    int n = (int)((idx * 2) % N_DIM);
    int k4 = (int)((idx * 2) / N_DIM);
    uint2 w = *(const uint2*)(qw + (size_t)k4 * N_DIM + n);
    int z0 = zeros[n], z1 = zeros[n + 1];
    __half2 zc;
    zc = __halves2half2(__float2half_rn(1024.0f + (float)z0),
                        __float2half_rn(1024.0f + (float)z1));
    __half* dst = g_wt + (size_t)(4 * k4) * N_DIM + n;
#pragma unroll
    for (int j = 0; j < 4; j++) {
        uint32_t t = __byte_perm(w.x, w.y, (uint32_t)(j | ((4 + j) << 8)));
        t = (t & 0x00FF00FFu) | 0x64006400u;   // {1024+b0, 1024+b1} fp16x2
        __half2 h = __hsub2(*(__half2*)&t, zc);
        *(__half2*)(dst + (size_t)j * N_DIM) = h;
    }
}

// ---------------------------------------------------------------------------
__device__ __forceinline__ uint32_t smem_u32(const void* p) {
    return (uint32_t)__cvta_generic_to_shared(p);
}
__device__ __forceinline__ void ldsm_x4(uint32_t& r0, uint32_t& r1,
                                        uint32_t& r2, uint32_t& r3,
                                        uint32_t addr) {
    asm volatile("ldmatrix.sync.aligned.m8n8.x4.shared.b16 {%0,%1,%2,%3}, [%4];"
                 : "=r"(r0), "=r"(r1), "=r"(r2), "=r"(r3) : "r"(addr));
}
__device__ __forceinline__ void ldsm_x4_t(uint32_t& r0, uint32_t& r1,
                                          uint32_t& r2, uint32_t& r3,
                                          uint32_t addr) {
    asm volatile("ldmatrix.sync.aligned.m8n8.x4.trans.shared.b16 {%0,%1,%2,%3}, [%4];"
                 : "=r"(r0), "=r"(r1), "=r"(r2), "=r"(r3) : "r"(addr));
}
__device__ __forceinline__ void mma_16816(float c[4], const uint32_t a[4],
                                          const uint32_t b[2]) {
    asm volatile(
        "mma.sync.aligned.m16n8k16.row.col.f32.f16.f16.f32 "
        "{%0,%1,%2,%3}, {%4,%5,%6,%7}, {%8,%9}, {%0,%1,%2,%3};"
        : "+f"(c[0]), "+f"(c[1]), "+f"(c[2]), "+f"(c[3])
        : "r"(a[0]), "r"(a[1]), "r"(a[2]), "r"(a[3]), "r"(b[0]), "r"(b[1]));
}
__device__ __forceinline__ void cp16(uint32_t dst, const void* src) {
    asm volatile("cp.async.cg.shared.global [%0], [%1], 16;"
                 :: "r"(dst), "l"(src) : "memory");
}

// ---------------------------------------------------------------------------
// GEMM: block 128x256, 8 warps (2x4), warp tile 64x64, BK=64, 3-stage cp.async
// ---------------------------------------------------------------------------
__global__ void __launch_bounds__(256, 1)
qgemm_kernel(const float* __restrict__ scales, const float* __restrict__ bias,
             float* __restrict__ out) {
    extern __shared__ char smem[];
    const uint32_t sbase = smem_u32(smem);

    const int tid = threadIdx.x;
    const int lane = tid & 31;
    const int wid = tid >> 5;
    const int warp_m = wid & 1;
    const int warp_n = wid >> 1;
    const int bm0 = blockIdx.y * BM;
    const int bn0 = blockIdx.x * BN;

    // fill mappings
    const int rowA = tid >> 1;           // 0..127
    const int cA = (tid & 1) * 4;        // 4 chunks of 16B each
    const __half* Ag = g_xh + (size_t)(bm0 + rowA) * K_DIM;
    const int rowB = tid >> 2;           // 0..63 (k rows)
    const int cB = (tid & 3) * 8;        // 8 chunks of 16B each
    const __half* Bgk = g_wt + (size_t)rowB * N_DIM + bn0;

    float acc[4][8][4];
#pragma unroll
    for (int mi = 0; mi < 4; mi++)
#pragma unroll
        for (int ni = 0; ni < 8; ni++)
#pragma unroll
            for (int t = 0; t < 4; t++) acc[mi][ni][t] = 0.0f;

#define FILL_STAGE(S, KTILE)                                                   \
    do {                                                                       \
        uint32_t ab = sbase + (uint32_t)((S) * STAGE_SZ);                      \
        uint32_t bb = ab + A_SZ;                                               \
        _Pragma("unroll") for (int j = 0; j < 4; j++)                          \
            cp16(ab + (uint32_t)(rowA * LDA_B + (cA + j) * 16),                \
                 Ag + (KTILE) * BK + (cA + j) * 8);                            \
        _Pragma("unroll") for (int j = 0; j < 8; j++)                          \
            cp16(bb + (uint32_t)(rowB * LDB_B + (cB + j) * 16),                \
                 Bgk + (size_t)(KTILE) * BK * N_DIM + (cB + j) * 8);           \
        asm volatile("cp.async.commit_group;" ::: "memory");                   \
    } while (0)

    FILL_STAGE(0, 0);
    FILL_STAGE(1, 1);

    const int g = lane >> 3, lr = lane & 7;
    uint32_t af[2][4][4];
    uint32_t bf[2][8][2];

#define LDSM_KS(BUFI, AB, BB, KS)                                              \
    do {                                                                       \
        _Pragma("unroll") for (int mi = 0; mi < 4; mi++) {                     \
            int row = warp_m * 64 + mi * 16 + (g & 1) * 8 + lr;                \
            int col = (KS) * 16 + (g >> 1) * 8;                                \
            ldsm_x4(af[BUFI][mi][0], af[BUFI][mi][1], af[BUFI][mi][2],         \
                    af[BUFI][mi][3], (AB) + (uint32_t)(row * LDA_B + col * 2));\
        }                                                                      \
        _Pragma("unroll") for (int nj = 0; nj < 4; nj++) {                     \
            int m = lane >> 3;                                                 \
            int krow = (KS) * 16 + (m & 1) * 8 + (lane & 7);                   \
            int noff = warp_n * 64 + nj * 16 + (m >> 1) * 8;                   \
            uint32_t r0, r1, r2, r3;                                           \
            ldsm_x4_t(r0, r1, r2, r3,                                          \
                      (BB) + (uint32_t)(krow * LDB_B + noff * 2));             \
            bf[BUFI][2 * nj][0] = r0;     bf[BUFI][2 * nj][1] = r1;            \
            bf[BUFI][2 * nj + 1][0] = r2; bf[BUFI][2 * nj + 1][1] = r3;        \
        }                                                                      \
    } while (0)

#pragma unroll 1
    for (int kt = 0; kt < KT; kt++) {
        asm volatile("cp.async.wait_group 1;" ::: "memory");
        __syncthreads();
        if (kt + 2 < KT) FILL_STAGE((kt + 2) % STAGES, kt + 2);

        const uint32_t ab = sbase + (uint32_t)((kt % STAGES) * STAGE_SZ);
        const uint32_t bb = ab + A_SZ;

        LDSM_KS(0, ab, bb, 0);
#pragma unroll
        for (int ks = 0; ks < 4; ks++) {
            if (ks < 3) LDSM_KS((ks + 1) & 1, ab, bb, ks + 1);
            const int cur = ks & 1;
#pragma unroll
            for (int ni = 0; ni < 8; ni++)
#pragma unroll
                for (int mi = 0; mi < 4; mi++)
                    mma_16816(acc[mi][ni], af[cur][mi], bf[cur][ni]);
        }
    }

    // ---------------- epilogue ----------------
    const int m0 = bm0 + warp_m * 64;
    const int n0w = bn0 + warp_n * 64;
    const int elr = lane >> 2;
    const int elc = (lane & 3) * 2;
#pragma unroll
    for (int ni = 0; ni < 8; ni++) {
        const int col = n0w + ni * 8 + elc;
        const float s0 = scales[col], s1 = scales[col + 1];
        const float b0 = bias[col], b1 = bias[col + 1];
#pragma unroll
        for (int mi = 0; mi < 4; mi++) {
            const int r0 = m0 + mi * 16 + elr;
            float2 v0 = make_float2(acc[mi][ni][0] * s0 + b0,
                                    acc[mi][ni][1] * s1 + b1);
            *(float2*)(out + (size_t)r0 * N_DIM + col) = v0;
            float2 v1 = make_float2(acc[mi][ni][2] * s0 + b0,
                                    acc[mi][ni][3] * s1 + b1);
            *(float2*)(out + (size_t)(r0 + 8) * N_DIM + col) = v1;
        }
    }
}

// ---------------------------------------------------------------------------
extern "C" void kernel_launch(void* const* d_in, const int* in_sizes, int n_in,
                              void* d_out, int out_size) {
    const float* x = (const float*)d_in[0];
    const uint32_t* qw = (const uint32_t*)d_in[1];
    const float* scales = (const float*)d_in[2];
    const int* zeros = (const int*)d_in[3];
    const float* bias = (const float*)d_in[4];
    float* out = (float*)d_out;

    convert_x_kernel<<<(M_DIM * K_DIM) / (256 * 8), 256>>>(x);

    // (K/4)*N words, 2 per thread
    dequant_kernel<<<(K_DIM / 4) * N_DIM / (256 * 2), 256>>>(qw, zeros);

    cudaFuncSetAttribute(qgemm_kernel,
                         cudaFuncAttributeMaxDynamicSharedMemorySize, SMEM_TOTAL);
    dim3 grid(N_DIM / BN, M_DIM / BM);  // 43 x 16
    qgemm_kernel<<<grid, 256, SMEM_TOTAL>>>(scales, bias, out);
}

// round 5
// speedup vs baseline: 1.0133x; 1.0133x over previous
#include <cuda_runtime.h>
#include <cuda_fp16.h>
#include <stdint.h>

#define M_DIM 2048
#define N_DIM 11008
#define K_DIM 4096

#define BM 128
#define BN 128
#define BK 32
#define KT (K_DIM / BK)      // 128
#define LDA 40               // halves per A row (32 + 8 pad) = 80 B
#define LDB 40               // halves per B n-row
#define A_SZ (BM * LDA * 2)  // 10240 B
#define B_SZ (BN * LDB * 2)  // 10240 B
#define STAGE_SZ (A_SZ + B_SZ)        // 20480 B
#define SMEM_TOTAL (2 * STAGE_SZ)     // 40960 B

__device__ __half g_xh[(size_t)M_DIM * K_DIM];

// ---------------------------------------------------------------------------
__global__ void convert_x_kernel(const float* __restrict__ x) {
    size_t i = ((size_t)blockIdx.x * blockDim.x + threadIdx.x) * 8;
    float4 f0 = *(const float4*)(x + i);
    float4 f1 = *(const float4*)(x + i + 4);
    __half2 h01 = __floats2half2_rn(f0.x, f0.y);
    __half2 h23 = __floats2half2_rn(f0.z, f0.w);
    __half2 h45 = __floats2half2_rn(f1.x, f1.y);
    __half2 h67 = __floats2half2_rn(f1.z, f1.w);
    uint4 v;
    v.x = *(uint32_t*)&h01; v.y = *(uint32_t*)&h23;
    v.z = *(uint32_t*)&h45; v.w = *(uint32_t*)&h67;
    *(uint4*)(g_xh + i) = v;
}

// ---------------------------------------------------------------------------
__device__ __forceinline__ uint32_t smem_u32(const void* p) {
    return (uint32_t)__cvta_generic_to_shared(p);
}
__device__ __forceinline__ void ldsm_x4(uint32_t& r0, uint32_t& r1,
                                        uint32_t& r2, uint32_t& r3,
                                        uint32_t addr) {
    asm volatile("ldmatrix.sync.aligned.m8n8.x4.shared.b16 {%0,%1,%2,%3}, [%4];"
                 : "=r"(r0), "=r"(r1), "=r"(r2), "=r"(r3) : "r"(addr));
}
__device__ __forceinline__ void mma_16816(float c[4], const uint32_t a[4],
                                          const uint32_t b[2]) {
    asm volatile(
        "mma.sync.aligned.m16n8k16.row.col.f32.f16.f16.f32 "
        "{%0,%1,%2,%3}, {%4,%5,%6,%7}, {%8,%9}, {%0,%1,%2,%3};"
        : "+f"(c[0]), "+f"(c[1]), "+f"(c[2]), "+f"(c[3])
        : "r"(a[0]), "r"(a[1]), "r"(a[2]), "r"(a[3]), "r"(b[0]), "r"(b[1]));
}
__device__ __forceinline__ void cp16(uint32_t dst, const void* src) {
    asm volatile("cp.async.cg.shared.global [%0], [%1], 16;"
                 :: "r"(dst), "l"(src) : "memory");
}

// ---------------------------------------------------------------------------
// out[m,n] = scale[n] * sum_k x[m,k]*(W_int[k,n]-zero[n]) + bias[n]
// block 128x128, 4 warps (2x2), warp tile 64x64, BK=32, 2-stage
// ---------------------------------------------------------------------------
__global__ void __launch_bounds__(128, 3)
qgemm_kernel(const uint32_t* __restrict__ qw, const float* __restrict__ scales,
             const int* __restrict__ zeros, const float* __restrict__ bias,
             float* __restrict__ out) {
    extern __shared__ char smem[];
    const uint32_t sbase = smem_u32(smem);

    const int tid = threadIdx.x;
    const int lane = tid & 31;
    const int wid = tid >> 5;
    const int warp_m = wid & 1;
    const int warp_n = wid >> 1;
    const int bm0 = blockIdx.y * BM;
    const int bn0 = blockIdx.x * BN;

    // ---- A fill: cp.async, thread owns one row (4 x 16B chunks) ----
    const int rowA = tid;  // 0..127
    const __half* Ag = g_xh + (size_t)(bm0 + rowA) * K_DIM;

    // ---- B fill: thread owns column n = tid, 8 packed words per k-tile ----
    const int n_loc = tid;
    const int stgB = (n_loc >> 3) & 7;   // phase stagger for STS
    const uint32_t* Bg = qw + (size_t)bn0 + n_loc;
    const int zq = zeros[bn0 + n_loc];
    const __half2 zc = __half2half2(__float2half_rn(1024.0f + (float)zq));

    float acc[4][8][4];
#pragma unroll
    for (int mi = 0; mi < 4; mi++)
#pragma unroll
        for (int ni = 0; ni < 8; ni++)
#pragma unroll
            for (int t = 0; t < 4; t++) acc[mi][ni][t] = 0.0f;

    uint32_t br[8];

#define STS_B(STAGE_OFF)                                                       \
    do {                                                                       \
        char* Bs = smem + (STAGE_OFF) + A_SZ;                                  \
        _Pragma("unroll") for (int j = 0; j < 8; j++) {                        \
            int jj = (j + stgB) & 7;                                           \
            uint32_t w = br[jj];                                               \
            uint32_t lo = __byte_perm(w, 0x64646464u, 0x4140);                 \
            uint32_t hi = __byte_perm(w, 0x64646464u, 0x4342);                 \
            __half2 h0 = __hsub2(*(__half2*)&lo, zc);                          \
            __half2 h1 = __hsub2(*(__half2*)&hi, zc);                          \
            uint2 st; st.x = *(uint32_t*)&h0; st.y = *(uint32_t*)&h1;          \
            *(uint2*)(Bs + n_loc * (LDB * 2) + jj * 8) = st;                   \
        }                                                                      \
    } while (0)

    // ---------------- prologue: stage 0 ----------------
    {
#pragma unroll
        for (int c = 0; c < 4; c++)
            cp16(sbase + (uint32_t)(rowA * (LDA * 2) + c * 16), Ag + c * 8);
        asm volatile("cp.async.commit_group;" ::: "memory");
#pragma unroll
        for (int j = 0; j < 8; j++) br[j] = Bg[(size_t)j * N_DIM];
        STS_B(0);
        asm volatile("cp.async.wait_group 0;" ::: "memory");
        __syncthreads();
    }

    const int g = lane >> 3, lr = lane & 7;
    int buf = 0;
#pragma unroll 1
    for (int kt = 0; kt < KT; kt++) {
        const int nb = buf ^ 1;
        if (kt + 1 < KT) {
            const int k0 = (kt + 1) * BK;
#pragma unroll
            for (int c = 0; c < 4; c++)
                cp16(sbase + (uint32_t)(nb * STAGE_SZ + rowA * (LDA * 2) + c * 16),
                     Ag + k0 + c * 8);
            asm volatile("cp.async.commit_group;" ::: "memory");
#pragma unroll
            for (int j = 0; j < 8; j++)
                br[j] = Bg[(size_t)((kt + 1) * 8 + j) * N_DIM];
        }

        const uint32_t aB = sbase + (uint32_t)(buf * STAGE_SZ);
        const uint32_t bB = aB + A_SZ;
#pragma unroll
        for (int ks = 0; ks < 2; ks++) {
            uint32_t af[4][4];
#pragma unroll
            for (int mi = 0; mi < 4; mi++) {
                int row = warp_m * 64 + mi * 16 + (g & 1) * 8 + lr;
                int col = ks * 16 + (g >> 1) * 8;
                ldsm_x4(af[mi][0], af[mi][1], af[mi][2], af[mi][3],
                        aB + (uint32_t)(row * (LDA * 2) + col * 2));
            }
            uint32_t bf[8][2];
#pragma unroll
            for (int nj = 0; nj < 4; nj++) {
                int nrow = warp_n * 64 + nj * 16 + (g >> 1) * 8 + lr;
                int col = ks * 16 + (g & 1) * 8;
                uint32_t r0, r1, r2, r3;
                ldsm_x4(r0, r1, r2, r3,
                        bB + (uint32_t)(nrow * (LDB * 2) + col * 2));
                bf[2 * nj][0] = r0;     bf[2 * nj][1] = r1;
                bf[2 * nj + 1][0] = r2; bf[2 * nj + 1][1] = r3;
            }
#pragma unroll
            for (int ni = 0; ni < 8; ni++)
#pragma unroll
                for (int mi = 0; mi < 4; mi++)
                    mma_16816(acc[mi][ni], af[mi], bf[ni]);
        }

        if (kt + 1 < KT) {
            STS_B(nb * STAGE_SZ);
            asm volatile("cp.async.wait_group 0;" ::: "memory");
            __syncthreads();
        }
        buf ^= 1;
    }

    // ---------------- epilogue ----------------
    const int m0 = bm0 + warp_m * 64;
    const int n0w = bn0 + warp_n * 64;
    const int elr = lane >> 2;
    const int elc = (lane & 3) * 2;
#pragma unroll
    for (int ni = 0; ni < 8; ni++) {
        const int col = n0w + ni * 8 + elc;
        const float s0 = scales[col], s1 = scales[col + 1];
        const float b0 = bias[col], b1 = bias[col + 1];
#pragma unroll
        for (int mi = 0; mi < 4; mi++) {
            const int r0 = m0 + mi * 16 + elr;
            float2 v0 = make_float2(acc[mi][ni][0] * s0 + b0,
                                    acc[mi][ni][1] * s1 + b1);
            *(float2*)(out + (size_t)r0 * N_DIM + col) = v0;
            float2 v1 = make_float2(acc[mi][ni][2] * s0 + b0,
                                    acc[mi][ni][3] * s1 + b1);
            *(float2*)(out + (size_t)(r0 + 8) * N_DIM + col) = v1;
        }
    }
}

// ---------------------------------------------------------------------------
extern "C" void kernel_launch(void* const* d_in, const int* in_sizes, int n_in,
                              void* d_out, int out_size) {
    const float* x = (const float*)d_in[0];
    const uint32_t* qw = (const uint32_t*)d_in[1];
    const float* scales = (const float*)d_in[2];
    const int* zeros = (const int*)d_in[3];
    const float* bias = (const float*)d_in[4];
    float* out = (float*)d_out;

    convert_x_kernel<<<(M_DIM * K_DIM) / (256 * 8), 256>>>(x);

    cudaFuncSetAttribute(qgemm_kernel,
                         cudaFuncAttributeMaxDynamicSharedMemorySize, SMEM_TOTAL);
    dim3 grid(N_DIM / BN, M_DIM / BM);  // 86 x 16
    qgemm_kernel<<<grid, 128, SMEM_TOTAL>>>(qw, scales, zeros, bias, out);
}

// round 6
// speedup vs baseline: 1.4031x; 1.3847x over previous
#include <cuda_runtime.h>
#include <cuda_fp16.h>
#include <stdint.h>

#define M_DIM 2048
#define N_DIM 11008
#define K_DIM 4096

#define BM 128
#define BN 256
#define BK 64
#define KT (K_DIM / BK)          // 64
#define STAGES 3
#define A_STRIDE 160             // bytes per A row (128 data + 32 pad)
#define A_STG (BM * A_STRIDE)    // 20480
#define SMEM_TOTAL (STAGES * A_STG)  // 61440

__device__ __half g_xh[(size_t)M_DIM * K_DIM];

// ---------------------------------------------------------------------------
__global__ void convert_x_kernel(const float* __restrict__ x) {
    size_t i = ((size_t)blockIdx.x * blockDim.x + threadIdx.x) * 8;
    float4 f0 = *(const float4*)(x + i);
    float4 f1 = *(const float4*)(x + i + 4);
    __half2 h01 = __floats2half2_rn(f0.x, f0.y);
    __half2 h23 = __floats2half2_rn(f0.z, f0.w);
    __half2 h45 = __floats2half2_rn(f1.x, f1.y);
    __half2 h67 = __floats2half2_rn(f1.z, f1.w);
    uint4 v;
    v.x = *(uint32_t*)&h01; v.y = *(uint32_t*)&h23;
    v.z = *(uint32_t*)&h45; v.w = *(uint32_t*)&h67;
    *(uint4*)(g_xh + i) = v;
}

// ---------------------------------------------------------------------------
__device__ __forceinline__ uint32_t smem_u32(const void* p) {
    return (uint32_t)__cvta_generic_to_shared(p);
}
__device__ __forceinline__ void lds64(uint32_t& lo, uint32_t& hi, uint32_t a) {
    asm volatile("ld.shared.v2.u32 {%0,%1}, [%2];" : "=r"(lo), "=r"(hi) : "r"(a));
}
__device__ __forceinline__ void mma_16816(float c[4], const uint32_t a[4],
                                          const uint32_t b[2]) {
    asm volatile(
        "mma.sync.aligned.m16n8k16.row.col.f32.f16.f16.f32 "
        "{%0,%1,%2,%3}, {%4,%5,%6,%7}, {%8,%9}, {%0,%1,%2,%3};"
        : "+f"(c[0]), "+f"(c[1]), "+f"(c[2]), "+f"(c[3])
        : "r"(a[0]), "r"(a[1]), "r"(a[2]), "r"(a[3]), "r"(b[0]), "r"(b[1]));
}
__device__ __forceinline__ void cp16(uint32_t dst, const void* src) {
    asm volatile("cp.async.cg.shared.global [%0], [%1], 16;"
                 :: "r"(dst), "l"(src) : "memory");
}

// ---------------------------------------------------------------------------
// out[m,n] = scale[n]*sum_k x[m,k]*(W[k,n]-zero[n]) + bias[n]
// block 128x256, 8 warps (2x4), warp tile 64x64, BK=64.
// B fragments built directly from packed gmem words (k-permuted MMA).
// ---------------------------------------------------------------------------
__global__ void __launch_bounds__(256)
qgemm_kernel(const uint32_t* __restrict__ qw, const float* __restrict__ scales,
             const int* __restrict__ zeros, const float* __restrict__ bias,
             float* __restrict__ out) {
    extern __shared__ char smem[];
    const uint32_t sbase = smem_u32(smem);

    const int tid = threadIdx.x;
    const int lane = tid & 31;
    const int wid = tid >> 5;
    const int warp_m = wid & 1;   // 0..1
    const int warp_n = wid >> 1;  // 0..3
    const int bm0 = blockIdx.x * BM;
    const int bn0 = blockIdx.y * BN;

    // ---- A fill mapping (cp.async): 2 threads per row ----
    const int rowA = tid >> 1;
    const int halfA = tid & 1;
    const __half* Ag = g_xh + (size_t)(bm0 + rowA) * K_DIM + halfA * 32;

    // ---- B fragment gmem base: lane owns (k4 = lane%4, n = lane/4) ----
    const int nb = bn0 + warp_n * 64 + (lane >> 2);
    const uint32_t* Bg = qw + (size_t)(lane & 3) * N_DIM + nb;

    // per-nj zero constants (n = nb + nj*8), exact fp16
    __half2 zc[8];
#pragma unroll
    for (int nj = 0; nj < 8; nj++)
        zc[nj] = __half2half2(
            __float2half_rn(1024.0f + (float)zeros[nb + nj * 8]));

    float acc[4][8][4];
#pragma unroll
    for (int mi = 0; mi < 4; mi++)
#pragma unroll
        for (int ni = 0; ni < 8; ni++)
#pragma unroll
            for (int t = 0; t < 4; t++) acc[mi][ni][t] = 0.0f;

#define FILL_A(S, KTILE)                                                       \
    do {                                                                       \
        uint32_t db = sbase + (uint32_t)((S) * A_STG + rowA * A_STRIDE +       \
                                         halfA * 64);                          \
        const __half* sp = Ag + (KTILE) * BK;                                  \
        _Pragma("unroll") for (int c = 0; c < 4; c++)                          \
            cp16(db + c * 16, sp + c * 8);                                     \
        asm volatile("cp.async.commit_group;" ::: "memory");                   \
    } while (0)

    // ---- prologue ----
    FILL_A(0, 0);
    FILL_A(1, 1);
    uint32_t br[4][8];   // [k16][nj] packed words, current tile
#pragma unroll
    for (int k16 = 0; k16 < 4; k16++)
#pragma unroll
        for (int nj = 0; nj < 8; nj++)
            br[k16][nj] = Bg[(size_t)(k16 * 4) * N_DIM + nj * 8];
    asm volatile("cp.async.wait_group 1;" ::: "memory");
    __syncthreads();

    const int arow = lane >> 2;    // 0..7
    const int acol = (lane & 3) * 8;  // byte offset within 32B k16 block

#pragma unroll 1
    for (int kt = 0; kt < KT; kt++) {
        if (kt + 2 < KT) FILL_A((kt + 2) % STAGES, kt + 2);
        const uint32_t abase = sbase + (uint32_t)((kt % STAGES) * A_STG) +
                               (uint32_t)(warp_m * 64 + arow) * A_STRIDE + acol;
        const int ktn = (kt + 1) & (KT - 1);   // next tile (wraps, harmless)

#pragma unroll
        for (int k16 = 0; k16 < 4; k16++) {
            // A fragments: k-major smem, slot-k = 16*k16 + 4*(lane%4)+{0..3}
            uint32_t af[4][4];
#pragma unroll
            for (int mi = 0; mi < 4; mi++) {
                uint32_t a0 = abase + (uint32_t)(mi * 16) * A_STRIDE + k16 * 32;
                uint32_t lo0, hi0, lo1, hi1;
                lds64(lo0, hi0, a0);
                lds64(lo1, hi1, a0 + 8 * A_STRIDE);
                af[mi][0] = lo0; af[mi][1] = lo1;
                af[mi][2] = hi0; af[mi][3] = hi1;
            }
            // B fragments: dequant in registers, then prefetch next tile word
#pragma unroll
            for (int nj = 0; nj < 8; nj++) {
                uint32_t w = br[k16][nj];
                uint32_t lo = __byte_perm(w, 0x64646464u, 0x4140);
                uint32_t hi = __byte_perm(w, 0x64646464u, 0x4342);
                __half2 h0 = __hsub2(*(__half2*)&lo, zc[nj]);
                __half2 h1 = __hsub2(*(__half2*)&hi, zc[nj]);
                uint32_t bf[2];
                bf[0] = *(uint32_t*)&h0;
                bf[1] = *(uint32_t*)&h1;
                br[k16][nj] = Bg[(size_t)(ktn * 16 + k16 * 4) * N_DIM + nj * 8];
#pragma unroll
                for (int mi = 0; mi < 4; mi++)
                    mma_16816(acc[mi][nj], af[mi], bf);
            }
        }

        if (kt + 2 < KT) {
            asm volatile("cp.async.wait_group 1;" ::: "memory");
        } else {
            asm volatile("cp.async.wait_group 0;" ::: "memory");
        }
        __syncthreads();
    }

    // ---- epilogue ----
    const int m0 = bm0 + warp_m * 64;
    const int n0w = bn0 + warp_n * 64;
    const int elr = lane >> 2;
    const int elc = (lane & 3) * 2;
#pragma unroll
    for (int ni = 0; ni < 8; ni++) {
        const int col = n0w + ni * 8 + elc;
        const float s0 = scales[col], s1 = scales[col + 1];
        const float b0 = bias[col], b1 = bias[col + 1];
#pragma unroll
        for (int mi = 0; mi < 4; mi++) {
            const int r0 = m0 + mi * 16 + elr;
            float2 v0 = make_float2(acc[mi][ni][0] * s0 + b0,
                                    acc[mi][ni][1] * s1 + b1);
            *(float2*)(out + (size_t)r0 * N_DIM + col) = v0;
            float2 v1 = make_float2(acc[mi][ni][2] * s0 + b0,
                                    acc[mi][ni][3] * s1 + b1);
            *(float2*)(out + (size_t)(r0 + 8) * N_DIM + col) = v1;
        }
    }
}

// ---------------------------------------------------------------------------
extern "C" void kernel_launch(void* const* d_in, const int* in_sizes, int n_in,
                              void* d_out, int out_size) {
    const float* x = (const float*)d_in[0];
    const uint32_t* qw = (const uint32_t*)d_in[1];
    const float* scales = (const float*)d_in[2];
    const int* zeros = (const int*)d_in[3];
    const float* bias = (const float*)d_in[4];
    float* out = (float*)d_out;

    convert_x_kernel<<<(M_DIM * K_DIM) / (256 * 8), 256>>>(x);

    cudaFuncSetAttribute(qgemm_kernel,
                         cudaFuncAttributeMaxDynamicSharedMemorySize, SMEM_TOTAL);
    dim3 grid(M_DIM / BM, N_DIM / BN);  // 16 x 43 (m-blocks fastest: B L2 reuse)
    qgemm_kernel<<<grid, 256, SMEM_TOTAL>>>(qw, scales, zeros, bias, out);
}